// round 8
// baseline (speedup 1.0000x reference)
#include <cuda_runtime.h>
#include <cuda_fp16.h>
#include <cstdint>

#define B_DIM 4
#define C_DIM 128
#define L_DIM 24
#define HW_DIM 4096

#define SK   136          // fp16 row stride in elements
#define ROWB (SK * 2)     // 272 bytes/row (weights + B buffer)
#define XSW  132          // fp32 stage row stride in floats (528B)

#define SM_MHI 0
#define SM_WHI 34816
#define SM_BHI 69632
#define SM_XS  104448
#define SMEM_BYTES (104448 + 128 * XSW * 4)   // 172032

#define NTHREADS 512

__device__ __align__(16) float g_M[C_DIM * C_DIM];             // (U@V)[c][k]
__device__ __align__(16) float g_decay[B_DIM * L_DIM * C_DIM]; // exp(-softplus(lam)*dt)

// ---------------- helpers ----------------
__device__ __forceinline__ uint32_t smem_u32(const void* p) {
    uint32_t a;
    asm("{ .reg .u64 t; cvta.to.shared.u64 t, %1; cvt.u32.u64 %0, t; }" : "=r"(a) : "l"(p));
    return a;
}
__device__ __forceinline__ void ldsm4(uint32_t* r, uint32_t a) {
    asm volatile("ldmatrix.sync.aligned.m8n8.x4.shared.b16 {%0,%1,%2,%3}, [%4];"
                 : "=r"(r[0]), "=r"(r[1]), "=r"(r[2]), "=r"(r[3]) : "r"(a));
}
__device__ __forceinline__ void ldsm4t(uint32_t* r, uint32_t a) {
    asm volatile("ldmatrix.sync.aligned.m8n8.x4.trans.shared.b16 {%0,%1,%2,%3}, [%4];"
                 : "=r"(r[0]), "=r"(r[1]), "=r"(r[2]), "=r"(r[3]) : "r"(a));
}
__device__ __forceinline__ void mma16816(float* d, const uint32_t* a, const uint32_t* b) {
    asm volatile("mma.sync.aligned.m16n8k16.row.col.f32.f16.f16.f32 "
                 "{%0,%1,%2,%3}, {%4,%5,%6,%7}, {%8,%9}, {%0,%1,%2,%3};"
                 : "+f"(d[0]), "+f"(d[1]), "+f"(d[2]), "+f"(d[3])
                 : "r"(a[0]), "r"(a[1]), "r"(a[2]), "r"(a[3]), "r"(b[0]), "r"(b[1]));
}
__device__ __forceinline__ uint32_t pack_h2(float x0, float x1) {
    uint32_t r;
    asm("cvt.rn.f16x2.f32 %0, %1, %2;" : "=r"(r) : "f"(x1), "f"(x0));
    return r;
}
#define CP_ASYNC16(dst, src) \
    asm volatile("cp.async.ca.shared.global [%0], [%1], 16;" :: "r"(dst), "l"(src))
#define CP_COMMIT()  asm volatile("cp.async.commit_group;")
#define CP_WAIT0()   asm volatile("cp.async.wait_group 0;")

// ---------------- precompute ----------------
__global__ void precompute_kernel(const float* __restrict__ lam,
                                  const float* __restrict__ U,
                                  const float* __restrict__ V,
                                  const float* __restrict__ listT) {
    int tid = threadIdx.x;
    if (blockIdx.x < 64) {
        int e = blockIdx.x * 256 + tid;
        int c = e >> 7, k = e & 127;
        float s0 = 0.f, s1 = 0.f;
        #pragma unroll 8
        for (int r = 0; r < 64; r += 2) {
            s0 += U[c * 64 + r] * V[r * C_DIM + k];
            s1 += U[c * 64 + r + 1] * V[(r + 1) * C_DIM + k];
        }
        g_M[e] = s0 + s1;
    } else {
        int idx = (blockIdx.x - 64) * 256 + tid;
        if (idx < B_DIM * L_DIM * C_DIM) {
            int c = idx & 127;
            int t = (idx >> 7) % L_DIM;
            int b = idx / (L_DIM * C_DIM);
            float sp = log1pf(expf(lam[c]));
            g_decay[idx] = expf(-sp * listT[b * L_DIM + t]);
        }
    }
}

// single-pass fp16 GEMM with double-buffered fragments, k=128
__device__ __forceinline__ void gemm128(uint32_t aB, uint32_t bB,
                                        int m0, int n0, int lane,
                                        float acc[2][4][4]) {
    const int arow = lane & 15;
    const int aq   = lane >> 4;
    const uint32_t aBase = aB + (uint32_t)((m0 + arow) * ROWB + aq * 16);
    const uint32_t bBase = bB + (uint32_t)(arow * ROWB + n0 * 2 + aq * 16);

    uint32_t ah[2][2][4], bv[2][2][4];
    ldsm4(ah[0][0], aBase);
    ldsm4(ah[0][1], aBase + 16 * ROWB);
    ldsm4t(bv[0][0], bBase);
    ldsm4t(bv[0][1], bBase + 32);

    #pragma unroll
    for (int ki = 0; ki < 8; ++ki) {
        const int cur = ki & 1, nxt = cur ^ 1;
        if (ki < 7) {
            uint32_t ak = aBase + (uint32_t)((ki + 1) * 32);
            uint32_t bk = bBase + (uint32_t)((ki + 1) * 16 * ROWB);
            ldsm4(ah[nxt][0], ak);
            ldsm4(ah[nxt][1], ak + 16 * ROWB);
            ldsm4t(bv[nxt][0], bk);
            ldsm4t(bv[nxt][1], bk + 32);
        }
        #pragma unroll
        for (int ng = 0; ng < 2; ++ng)
            #pragma unroll
            for (int hh = 0; hh < 2; ++hh) {
                const int nt = ng * 2 + hh;
                mma16816(acc[0][nt], ah[cur][0], bv[cur][ng] + hh * 2);
                mma16816(acc[1][nt], ah[cur][1], bv[cur][ng] + hh * 2);
            }
    }
}

// ---------------- main kernel ----------------
__global__ __launch_bounds__(NTHREADS, 1)
void recurrent_kernel(const float* __restrict__ x,
                      const float* __restrict__ h0,
                      const float* __restrict__ Wout,
                      float* __restrict__ out,
                      float* __restrict__ hfin) {
    extern __shared__ char smem[];
    const uint32_t sb = smem_u32(smem);
    float* XS = (float*)(smem + SM_XS);

    const int tid  = threadIdx.x;
    const int lane = tid & 31;
    const int wid  = tid >> 5;            // 0..15
    const int b    = blockIdx.x >> 5;
    const int s0   = (blockIdx.x & 31) * 128;
    const int wm   = wid & 3;
    const int wn   = wid >> 2;
    const int m0   = wm * 32;
    const int n0   = wn * 32;
    const int g    = lane >> 2;
    const int tq   = lane & 3;
    const size_t rstride = (size_t)L_DIM * HW_DIM;

    // cp.async / staging coords: warp wid owns rows {it*16 + wid}, lane covers 16B chunk
    const uint32_t xsRow = sb + SM_XS;

    // ---- issue cp.async for x(0) ----
    #pragma unroll
    for (int it = 0; it < 8; ++it) {
        int r = it * 16 + wid;
        CP_ASYNC16(xsRow + (uint32_t)(r * XSW * 4 + lane * 16),
                   x + ((size_t)(b * C_DIM + r) * L_DIM + 0) * HW_DIM + s0 + lane * 4);
    }
    CP_COMMIT();

    // ---- stationary weights (fp16) ----
    for (int e = tid; e < C_DIM * C_DIM; e += NTHREADS) {
        int r = e >> 7, k = e & 127;
        uint32_t off = (uint32_t)(r * ROWB + k * 2);
        *(__half*)(smem + SM_MHI + off) = __float2half_rn(g_M[e]);
        *(__half*)(smem + SM_WHI + off) = __float2half_rn(Wout[e]);
    }

    // ---- initial hidden state fragments ----
    float h[2][4][4];
    #pragma unroll
    for (int mt = 0; mt < 2; ++mt) {
        #pragma unroll
        for (int nt = 0; nt < 4; ++nt) {
            int c_lo = m0 + mt * 16 + g;
            int s    = s0 + n0 + nt * 8 + tq * 2;
            float2 v0 = *(const float2*)&h0[(size_t)(b * C_DIM + c_lo) * HW_DIM + s];
            float2 v1 = *(const float2*)&h0[(size_t)(b * C_DIM + c_lo + 8) * HW_DIM + s];
            h[mt][nt][0] = v0.x; h[mt][nt][1] = v0.y;
            h[mt][nt][2] = v1.x; h[mt][nt][3] = v1.y;
        }
    }

    CP_WAIT0();
    __syncthreads();  // weights + x(0) visible

    for (int t = 0; t < L_DIM; ++t) {
        // ---- stage x(t): XSTAGE fp32 -> f16 into BHI ----
        #pragma unroll
        for (int it = 0; it < 8; ++it) {
            int r = it * 16 + wid;
            float4 v = *(const float4*)&XS[r * XSW + lane * 4];
            uint2 hp = make_uint2(pack_h2(v.x, v.y), pack_h2(v.z, v.w));
            *(uint2*)(smem + SM_BHI + (uint32_t)(r * ROWB + lane * 8)) = hp;
        }
        __syncthreads();

        // ---- GEMM1: u = M @ x ----
        float acc[2][4][4];
        #pragma unroll
        for (int mt = 0; mt < 2; ++mt)
            #pragma unroll
            for (int nt = 0; nt < 4; ++nt)
                #pragma unroll
                for (int q = 0; q < 4; ++q) acc[mt][nt][q] = 0.f;
        gemm128(sb + SM_MHI, sb + SM_BHI, m0, n0, lane, acc);

        // ---- recurrence: h = decay(c)*h + u ----
        {
            const float* dk = &g_decay[(b * L_DIM + t) * C_DIM];
            #pragma unroll
            for (int mt = 0; mt < 2; ++mt) {
                float dA = __ldg(&dk[m0 + mt * 16 + g]);
                float dB = __ldg(&dk[m0 + mt * 16 + 8 + g]);
                #pragma unroll
                for (int nt = 0; nt < 4; ++nt) {
                    h[mt][nt][0] = dA * h[mt][nt][0] + acc[mt][nt][0];
                    h[mt][nt][1] = dA * h[mt][nt][1] + acc[mt][nt][1];
                    h[mt][nt][2] = dB * h[mt][nt][2] + acc[mt][nt][2];
                    h[mt][nt][3] = dB * h[mt][nt][3] + acc[mt][nt][3];
                }
            }
        }

        // ---- residual: exact fp32 x from XSTAGE into GEMM2 accumulators ----
        #pragma unroll
        for (int mt = 0; mt < 2; ++mt) {
            #pragma unroll
            for (int nt = 0; nt < 4; ++nt) {
                int c_lo = m0 + mt * 16 + g;
                int col  = n0 + nt * 8 + tq * 2;
                float2 r0 = *(const float2*)&XS[c_lo * XSW + col];
                float2 r1 = *(const float2*)&XS[(c_lo + 8) * XSW + col];
                acc[mt][nt][0] = r0.x; acc[mt][nt][1] = r0.y;
                acc[mt][nt][2] = r1.x; acc[mt][nt][3] = r1.y;
            }
        }
        __syncthreads();   // all reads of x (BHI + XSTAGE) done

        // ---- write h (f16) into BHI for GEMM2 ----
        #pragma unroll
        for (int mt = 0; mt < 2; ++mt) {
            #pragma unroll
            for (int nt = 0; nt < 4; ++nt) {
                int c_lo = m0 + mt * 16 + g;
                int scol = n0 + nt * 8 + tq * 2;
                uint32_t off0 = (uint32_t)(c_lo * ROWB + scol * 2);
                *(uint32_t*)(smem + SM_BHI + off0) = pack_h2(h[mt][nt][0], h[mt][nt][1]);
                *(uint32_t*)(smem + SM_BHI + off0 + 8 * ROWB) = pack_h2(h[mt][nt][2], h[mt][nt][3]);
            }
        }

        // ---- issue cp.async for x(t+1) into XSTAGE (overlaps GEMM2) ----
        {
            int tn = (t + 1 < L_DIM) ? t + 1 : t;
            #pragma unroll
            for (int it = 0; it < 8; ++it) {
                int r = it * 16 + wid;
                CP_ASYNC16(xsRow + (uint32_t)(r * XSW * 4 + lane * 16),
                           x + ((size_t)(b * C_DIM + r) * L_DIM + tn) * HW_DIM + s0 + lane * 4);
            }
            CP_COMMIT();
        }
        __syncthreads();   // BHI(h) visible

        // ---- GEMM2: out = x + Wout @ h ----
        gemm128(sb + SM_WHI, sb + SM_BHI, m0, n0, lane, acc);

        // ---- store output ----
        #pragma unroll
        for (int mt = 0; mt < 2; ++mt) {
            #pragma unroll
            for (int nt = 0; nt < 4; ++nt) {
                int d_lo = m0 + mt * 16 + g;
                float* po = out + ((size_t)(b * C_DIM + d_lo) * L_DIM + t) * HW_DIM
                                + s0 + n0 + nt * 8 + tq * 2;
                *(float2*)po = make_float2(acc[mt][nt][0], acc[mt][nt][1]);
                *(float2*)(po + 8 * rstride) = make_float2(acc[mt][nt][2], acc[mt][nt][3]);
            }
        }
        CP_WAIT0();
        __syncthreads();   // GEMM2 reads done + x(t+1) landed
    }

    // ---- final hidden state ----
    #pragma unroll
    for (int mt = 0; mt < 2; ++mt) {
        #pragma unroll
        for (int nt = 0; nt < 4; ++nt) {
            int c_lo = m0 + mt * 16 + g;
            int s    = s0 + n0 + nt * 8 + tq * 2;
            *(float2*)&hfin[(size_t)(b * C_DIM + c_lo) * HW_DIM + s] =
                make_float2(h[mt][nt][0], h[mt][nt][1]);
            *(float2*)&hfin[(size_t)(b * C_DIM + c_lo + 8) * HW_DIM + s] =
                make_float2(h[mt][nt][2], h[mt][nt][3]);
        }
    }
}

extern "C" void kernel_launch(void* const* d_in, const int* in_sizes, int n_in,
                              void* d_out, int out_size) {
    const float* x     = (const float*)d_in[0];
    const float* h0    = (const float*)d_in[1];
    const float* listT = (const float*)d_in[2];
    const float* lam   = (const float*)d_in[3];
    const float* U     = (const float*)d_in[4];
    const float* V     = (const float*)d_in[5];
    const float* Wout  = (const float*)d_in[6];

    float* out  = (float*)d_out;
    float* hfin = out + (size_t)B_DIM * C_DIM * L_DIM * HW_DIM;

    precompute_kernel<<<112, 256>>>(lam, U, V, listT);

    cudaFuncSetAttribute(recurrent_kernel,
                         cudaFuncAttributeMaxDynamicSharedMemorySize, SMEM_BYTES);
    recurrent_kernel<<<B_DIM * (HW_DIM / 128), NTHREADS, SMEM_BYTES>>>(x, h0, Wout, out, hfin);
}